// round 2
// baseline (speedup 1.0000x reference)
#include <cuda_runtime.h>
#include <cuda_bf16.h>
#include <math.h>

#define NB 32
#define SS 512
#define DM 256
#define NH 8
#define HDIM 64
#define NLAYER 5
#define FFD 1024
#define OUTD 4096
#define NT (NB*SS)     /* 16384 tokens */
#define QKV 512        /* H*HD */

// ---------------- scratch (no allocations allowed) ----------------
__device__ float g_h [NT*DM];
__device__ float g_q [NT*QKV];
__device__ float g_k [NT*QKV];
__device__ float g_v [NT*QKV];
__device__ float g_o [NT*QKV];
__device__ float g_ff[NT*FFD];
__device__ float g_p [NT*DM];
__device__ float g_pe[SS*DM];

// swizzled smem index: row-major 64-wide tile, column rotated by row
__device__ __forceinline__ int SWZ(int row, int col) { return row*64 + ((col + row) & 63); }

// ---------------- positional encoding table ----------------
__global__ void pe_kernel(float* __restrict__ pe) {
    int s = blockIdx.x;            // 0..511
    int d = threadIdx.x;           // 0..255
    int i = d >> 1;
    float expo = (float)(2*i) / (float)DM;
    float div = powf(10000.0f, expo);
    float ang = (float)s / div;
    pe[s*DM + d] = (d & 1) ? cosf(ang) : sinf(ang);
}

// ---------------- embedding + PE ----------------
__global__ void embed_kernel(const int* __restrict__ x, const float* __restrict__ emb,
                             const float* __restrict__ pe, float* __restrict__ h) {
    int t = blockIdx.x;            // token 0..NT-1
    int d = threadIdx.x;
    int tok = x[t];
    int s = t & (SS-1);
    h[t*DM + d] = emb[tok*DM + d] + pe[s*DM + d];
}

// ---------------- tiled SGEMM: C[N,M] = A[N,K] @ W[K,M] + bias, opt ReLU ----------------
// block 16x16, tile 64x64, BK=16, 4x4 per thread
__global__ void gemm_bias(const float* __restrict__ A, const float* __restrict__ W,
                          const float* __restrict__ bias, float* __restrict__ C,
                          int M, int K, int relu) {
    __shared__ float As[16*64];   // [k][m] swizzled
    __shared__ float Bs[16*64];   // [k][n] natural
    int tx = threadIdx.x, ty = threadIdx.y;
    int tid = ty*16 + tx;
    int row0 = blockIdx.y * 64;
    int col0 = blockIdx.x * 64;

    int am  = tid >> 2;            // 0..63
    int ak4 = (tid & 3) * 4;       // 0,4,8,12
    int bk  = tid >> 4;            // 0..15
    int bn4 = (tid & 15) * 4;      // 0..60

    float acc[4][4];
    #pragma unroll
    for (int i = 0; i < 4; i++)
        #pragma unroll
        for (int j = 0; j < 4; j++) acc[i][j] = 0.0f;

    for (int k0 = 0; k0 < K; k0 += 16) {
        float4 a4 = *(const float4*)(A + (size_t)(row0 + am)*K + k0 + ak4);
        As[SWZ(ak4+0, am)] = a4.x;
        As[SWZ(ak4+1, am)] = a4.y;
        As[SWZ(ak4+2, am)] = a4.z;
        As[SWZ(ak4+3, am)] = a4.w;
        float4 b4 = *(const float4*)(W + (size_t)(k0 + bk)*M + col0 + bn4);
        *(float4*)&Bs[bk*64 + bn4] = b4;
        __syncthreads();
        #pragma unroll
        for (int kk = 0; kk < 16; kk++) {
            float a[4], b[4];
            #pragma unroll
            for (int i = 0; i < 4; i++) a[i] = As[SWZ(kk, ty*4 + i)];
            #pragma unroll
            for (int j = 0; j < 4; j++) b[j] = Bs[kk*64 + tx*4 + j];
            #pragma unroll
            for (int i = 0; i < 4; i++)
                #pragma unroll
                for (int j = 0; j < 4; j++) acc[i][j] = fmaf(a[i], b[j], acc[i][j]);
        }
        __syncthreads();
    }
    #pragma unroll
    for (int i = 0; i < 4; i++) {
        int r = row0 + ty*4 + i;
        #pragma unroll
        for (int j = 0; j < 4; j++) {
            int c = col0 + tx*4 + j;
            float v = acc[i][j] + bias[c];
            if (relu) v = fmaxf(v, 0.0f);
            C[(size_t)r*M + c] = v;
        }
    }
}

// ---------------- fused causal flash attention ----------------
// grid: (S/64, B*H); block 16x16. Each block: one (b,h), 64 queries.
__global__ void attn_kernel(const float* __restrict__ Q, const float* __restrict__ K,
                            const float* __restrict__ V, float* __restrict__ O) {
    __shared__ float Qs[64*64];   // [d][q] swizzled
    __shared__ float KP[64*64];   // K as [d][k] swizzled; reused as P [k][q] swizzled
    __shared__ float Vs[64*64];   // [k][d] natural

    int tx = threadIdx.x, ty = threadIdx.y;
    int tid = ty*16 + tx;
    int lr  = tid >> 4;            // 0..15
    int d4  = (tid & 15) * 4;      // 0..60

    int bh = blockIdx.y;
    int b  = bh >> 3;
    int hh = bh & 7;
    int qt = blockIdx.x;
    int q0 = qt * 64;
    size_t base = ((size_t)b * SS) * QKV + hh * HDIM;   // + row*QKV + d

    // load Q tile transposed+swizzled
    #pragma unroll
    for (int rep = 0; rep < 4; rep++) {
        int q = rep*16 + lr;
        float4 v4 = *(const float4*)(Q + base + (size_t)(q0 + q)*QKV + d4);
        Qs[SWZ(d4+0, q)] = v4.x;
        Qs[SWZ(d4+1, q)] = v4.y;
        Qs[SWZ(d4+2, q)] = v4.z;
        Qs[SWZ(d4+3, q)] = v4.w;
    }

    float m[4], l[4], o[4][4];
    #pragma unroll
    for (int i = 0; i < 4; i++) {
        m[i] = -1e30f; l[i] = 0.0f;
        #pragma unroll
        for (int j = 0; j < 4; j++) o[i][j] = 0.0f;
    }

    for (int kt = 0; kt <= qt; kt++) {
        __syncthreads();  // protect KP/Vs from previous iteration readers
        #pragma unroll
        for (int rep = 0; rep < 4; rep++) {
            int k = rep*16 + lr;
            size_t roff = base + (size_t)(kt*64 + k)*QKV + d4;
            float4 kv = *(const float4*)(K + roff);
            KP[SWZ(d4+0, k)] = kv.x;
            KP[SWZ(d4+1, k)] = kv.y;
            KP[SWZ(d4+2, k)] = kv.z;
            KP[SWZ(d4+3, k)] = kv.w;
            float4 vv = *(const float4*)(V + roff);
            *(float4*)&Vs[k*64 + d4] = vv;
        }
        __syncthreads();

        // scores s[i][j] = q(ty*4+i) . k(tx*4+j)
        float s[4][4];
        #pragma unroll
        for (int i = 0; i < 4; i++)
            #pragma unroll
            for (int j = 0; j < 4; j++) s[i][j] = 0.0f;
        #pragma unroll 8
        for (int d = 0; d < 64; d++) {
            float a[4], bb[4];
            #pragma unroll
            for (int i = 0; i < 4; i++) a[i]  = Qs[SWZ(d, ty*4 + i)];
            #pragma unroll
            for (int j = 0; j < 4; j++) bb[j] = KP[SWZ(d, tx*4 + j)];
            #pragma unroll
            for (int i = 0; i < 4; i++)
                #pragma unroll
                for (int j = 0; j < 4; j++) s[i][j] = fmaf(a[i], bb[j], s[i][j]);
        }
        bool diag = (kt == qt);
        #pragma unroll
        for (int i = 0; i < 4; i++)
            #pragma unroll
            for (int j = 0; j < 4; j++) {
                float sv = s[i][j] * 0.125f;   // 1/sqrt(64)
                if (diag && (tx*4 + j) > (ty*4 + i)) sv = -1e30f;
                s[i][j] = sv;
            }

        // online softmax per row (16 threads of a half-warp share a row group)
        float pr[4][4];
        #pragma unroll
        for (int i = 0; i < 4; i++) {
            float mx = s[i][0];
            #pragma unroll
            for (int j = 1; j < 4; j++) mx = fmaxf(mx, s[i][j]);
            #pragma unroll
            for (int off = 8; off >= 1; off >>= 1)
                mx = fmaxf(mx, __shfl_xor_sync(0xffffffffu, mx, off, 16));
            float mn = fmaxf(m[i], mx);
            float corr = __expf(m[i] - mn);
            l[i] *= corr;
            #pragma unroll
            for (int j = 0; j < 4; j++) o[i][j] *= corr;
            float rs = 0.0f;
            #pragma unroll
            for (int j = 0; j < 4; j++) { pr[i][j] = __expf(s[i][j] - mn); rs += pr[i][j]; }
            #pragma unroll
            for (int off = 8; off >= 1; off >>= 1)
                rs += __shfl_xor_sync(0xffffffffu, rs, off, 16);
            l[i] += rs;
            m[i] = mn;
        }

        __syncthreads();  // everyone done reading KP as K
        // write P as [k][q] swizzled into KP
        #pragma unroll
        for (int i = 0; i < 4; i++)
            #pragma unroll
            for (int j = 0; j < 4; j++)
                KP[SWZ(tx*4 + j, ty*4 + i)] = pr[i][j];
        __syncthreads();

        // o[q][d] += P[q][k] * V[k][d]
        #pragma unroll 8
        for (int kk = 0; kk < 64; kk++) {
            float a[4], bb[4];
            #pragma unroll
            for (int i = 0; i < 4; i++) a[i]  = KP[SWZ(kk, ty*4 + i)];
            #pragma unroll
            for (int j = 0; j < 4; j++) bb[j] = Vs[kk*64 + tx*4 + j];
            #pragma unroll
            for (int i = 0; i < 4; i++)
                #pragma unroll
                for (int j = 0; j < 4; j++) o[i][j] = fmaf(a[i], bb[j], o[i][j]);
        }
    }

    #pragma unroll
    for (int i = 0; i < 4; i++) {
        float inv = 1.0f / l[i];
        int q = q0 + ty*4 + i;
        #pragma unroll
        for (int j = 0; j < 4; j++)
            O[base + (size_t)q*QKV + tx*4 + j] = o[i][j] * inv;
    }
}

// ---------------- fused residual add + LayerNorm (in place on h) ----------------
__global__ void add_ln_kernel(float* __restrict__ h, const float* __restrict__ r,
                              const float* __restrict__ s, const float* __restrict__ b) {
    __shared__ float red[12];
    int t = blockIdx.x;
    int d = threadIdx.x;      // 256 threads
    int lane = d & 31, w = d >> 5;

    float v = h[(size_t)t*DM + d] + r[(size_t)t*DM + d];

    float sum = v;
    #pragma unroll
    for (int off = 16; off >= 1; off >>= 1) sum += __shfl_xor_sync(0xffffffffu, sum, off);
    if (lane == 0) red[w] = sum;
    __syncthreads();
    if (d == 0) { float tt = 0; for (int i = 0; i < 8; i++) tt += red[i]; red[8] = tt; }
    __syncthreads();
    float mean = red[8] * (1.0f/DM);

    float dv = v - mean;
    float sq = dv*dv;
    #pragma unroll
    for (int off = 16; off >= 1; off >>= 1) sq += __shfl_xor_sync(0xffffffffu, sq, off);
    if (lane == 0) red[w] = sq;
    __syncthreads();
    if (d == 0) { float tt = 0; for (int i = 0; i < 8; i++) tt += red[i]; red[9] = tt; }
    __syncthreads();
    float var = red[9] * (1.0f/DM);

    h[(size_t)t*DM + d] = dv * rsqrtf(var + 1e-5f) * s[d] + b[d];
}

// ---------------- launch ----------------
extern "C" void kernel_launch(void* const* d_in, const int* in_sizes, int n_in,
                              void* d_out, int out_size) {
    (void)in_sizes; (void)n_in; (void)out_size;
    const int*   x    = (const int*)  d_in[0];
    const float* emb  = (const float*)d_in[1];
    const float* wq   = (const float*)d_in[2];
    const float* bq   = (const float*)d_in[3];
    const float* wk   = (const float*)d_in[4];
    const float* bk   = (const float*)d_in[5];
    const float* wv   = (const float*)d_in[6];
    const float* bv   = (const float*)d_in[7];
    const float* wo   = (const float*)d_in[8];
    const float* bo   = (const float*)d_in[9];
    const float* ln1s = (const float*)d_in[10];
    const float* ln1b = (const float*)d_in[11];
    const float* w1   = (const float*)d_in[12];
    const float* b1   = (const float*)d_in[13];
    const float* w2   = (const float*)d_in[14];
    const float* b2   = (const float*)d_in[15];
    const float* ln2s = (const float*)d_in[16];
    const float* ln2b = (const float*)d_in[17];
    const float* ow   = (const float*)d_in[18];
    const float* ob   = (const float*)d_in[19];
    float* out = (float*)d_out;

    float *h, *q, *k, *v, *o, *ff, *p, *pe;
    cudaGetSymbolAddress((void**)&h,  g_h);
    cudaGetSymbolAddress((void**)&q,  g_q);
    cudaGetSymbolAddress((void**)&k,  g_k);
    cudaGetSymbolAddress((void**)&v,  g_v);
    cudaGetSymbolAddress((void**)&o,  g_o);
    cudaGetSymbolAddress((void**)&ff, g_ff);
    cudaGetSymbolAddress((void**)&p,  g_p);
    cudaGetSymbolAddress((void**)&pe, g_pe);

    dim3 blk(16, 16);

    pe_kernel   <<<SS, DM>>>(pe);
    embed_kernel<<<NT, DM>>>(x, emb, pe, h);

    for (int i = 0; i < NLAYER; i++) {
        gemm_bias<<<dim3(QKV/64, NT/64), blk>>>(h, wq + (size_t)i*DM*QKV, bq + i*QKV, q, QKV, DM, 0);
        gemm_bias<<<dim3(QKV/64, NT/64), blk>>>(h, wk + (size_t)i*DM*QKV, bk + i*QKV, k, QKV, DM, 0);
        gemm_bias<<<dim3(QKV/64, NT/64), blk>>>(h, wv + (size_t)i*DM*QKV, bv + i*QKV, v, QKV, DM, 0);
        attn_kernel<<<dim3(SS/64, NB*NH), blk>>>(q, k, v, o);
        gemm_bias<<<dim3(DM/64, NT/64), blk>>>(o, wo + (size_t)i*QKV*DM, bo + i*DM, p, DM, QKV, 0);
        add_ln_kernel<<<NT, DM>>>(h, p, ln1s + i*DM, ln1b + i*DM);
        gemm_bias<<<dim3(FFD/64, NT/64), blk>>>(h, w1 + (size_t)i*DM*FFD, b1 + i*FFD, ff, FFD, DM, 1);
        gemm_bias<<<dim3(DM/64, NT/64), blk>>>(ff, w2 + (size_t)i*FFD*DM, b2 + i*DM, p, DM, FFD, 0);
        add_ln_kernel<<<NT, DM>>>(h, p, ln2s + i*DM, ln2b + i*DM);
    }

    gemm_bias<<<dim3(OUTD/64, NT/64), blk>>>(h, ow, ob, out, OUTD, DM, 0);
}

// round 4
// speedup vs baseline: 1.3416x; 1.3416x over previous
#include <cuda_runtime.h>
#include <cuda_bf16.h>
#include <math.h>

#define NB 32
#define SS 512
#define DM 256
#define NH 8
#define HDIM 64
#define NLAYER 5
#define FFD 1024
#define OUTD 4096
#define NT (NB*SS)     /* 16384 tokens */
#define QKV 512        /* H*HD */

// ---------------- scratch (no allocations allowed) ----------------
__device__ float g_h [NT*DM];
__device__ float g_q [NT*QKV];
__device__ float g_k [NT*QKV];
__device__ float g_v [NT*QKV];
__device__ float g_o [NT*QKV];
__device__ float g_ff[NT*FFD];
__device__ float g_p [NT*DM];
__device__ float g_pe[SS*DM];

// swizzled smem index (attention kernel): 64-wide tile, column rotated by row
__device__ __forceinline__ int SWZ(int row, int col) { return row*64 + ((col + row) & 63); }

// ---------------- positional encoding table ----------------
__global__ void pe_kernel(float* __restrict__ pe) {
    int s = blockIdx.x;
    int d = threadIdx.x;
    int i = d >> 1;
    float expo = (float)(2*i) / (float)DM;
    float div = powf(10000.0f, expo);
    float ang = (float)s / div;
    pe[s*DM + d] = (d & 1) ? cosf(ang) : sinf(ang);
}

// ---------------- embedding + PE ----------------
__global__ void embed_kernel(const int* __restrict__ x, const float* __restrict__ emb,
                             const float* __restrict__ pe, float* __restrict__ h) {
    int t = blockIdx.x;
    int d = threadIdx.x;
    int tok = x[t];
    int s = t & (SS-1);
    h[t*DM + d] = emb[tok*DM + d] + pe[s*DM + d];
}

// ---------------- tiled SGEMM: C[N,M] = A[N,K] @ W[K,M] + bias, opt ReLU ----------------
// 128x128x16 tiles, 256 threads, 8x8 per thread, double-buffered smem, float4 LDS only.
#define BM 128
#define BN 128
#define BK 16
#define ASTRIDE (BM + 4)   /* 132: float4-aligned, 2-way store conflict max */

__global__ void __launch_bounds__(256, 2)
gemm_bias(const float* __restrict__ A, const float* __restrict__ W,
          const float* __restrict__ bias, float* __restrict__ C,
          int M, int K, int relu) {
    __shared__ float As[2][BK][ASTRIDE];   // [k][m] transposed
    __shared__ float Bs[2][BK][BN];        // [k][n] natural

    int tid = threadIdx.x;
    int tx = tid & 15;          // 0..15 -> n
    int ty = tid >> 4;          // 0..15 -> m
    int row0 = blockIdx.y * BM;
    int col0 = blockIdx.x * BN;

    // A loader: float4 along K. rows tid/4 (+64), kcol (tid&3)*4
    int arow = tid >> 2;            // 0..63
    int acol = (tid & 3) * 4;       // 0,4,8,12
    // B loader: float4 along N. krow tid/32 (+8), ncol (tid&31)*4
    int brow = tid >> 5;            // 0..7
    int bcol = (tid & 31) * 4;      // 0..124

    const float* Ap = A + (size_t)(row0 + arow) * K + acol;
    const float* Bp = W + (size_t)brow * M + col0 + bcol;

    float acc[8][8];
    #pragma unroll
    for (int i = 0; i < 8; i++)
        #pragma unroll
        for (int j = 0; j < 8; j++) acc[i][j] = 0.0f;

    int ntiles = K / BK;

    // preload tile 0 into buffer 0
    {
        float4 a0 = *(const float4*)(Ap);
        float4 a1 = *(const float4*)(Ap + (size_t)64 * K);
        As[0][acol+0][arow]    = a0.x;
        As[0][acol+1][arow]    = a0.y;
        As[0][acol+2][arow]    = a0.z;
        As[0][acol+3][arow]    = a0.w;
        As[0][acol+0][arow+64] = a1.x;
        As[0][acol+1][arow+64] = a1.y;
        As[0][acol+2][arow+64] = a1.z;
        As[0][acol+3][arow+64] = a1.w;
        float4 b0 = *(const float4*)(Bp);
        float4 b1 = *(const float4*)(Bp + (size_t)8 * M);
        *(float4*)&Bs[0][brow][bcol]     = b0;
        *(float4*)&Bs[0][brow+8][bcol]   = b1;
    }
    __syncthreads();

    int ty4 = ty * 4, tx4 = tx * 4;

    for (int t = 0; t < ntiles; t++) {
        int cur = t & 1;
        float4 pa0, pa1, pb0, pb1;
        bool more = (t + 1 < ntiles);
        if (more) {
            const float* Ap2 = Ap + (t + 1) * BK;
            const float* Bp2 = Bp + (size_t)(t + 1) * BK * M;
            pa0 = *(const float4*)(Ap2);
            pa1 = *(const float4*)(Ap2 + (size_t)64 * K);
            pb0 = *(const float4*)(Bp2);
            pb1 = *(const float4*)(Bp2 + (size_t)8 * M);
        }

        #pragma unroll
        for (int kk = 0; kk < BK; kk++) {
            float a[8], b[8];
            *(float4*)&a[0] = *(const float4*)&As[cur][kk][ty4];
            *(float4*)&a[4] = *(const float4*)&As[cur][kk][ty4 + 64];
            *(float4*)&b[0] = *(const float4*)&Bs[cur][kk][tx4];
            *(float4*)&b[4] = *(const float4*)&Bs[cur][kk][tx4 + 64];
            #pragma unroll
            for (int i = 0; i < 8; i++)
                #pragma unroll
                for (int j = 0; j < 8; j++)
                    acc[i][j] = fmaf(a[i], b[j], acc[i][j]);
        }

        if (more) {
            int nxt = cur ^ 1;
            As[nxt][acol+0][arow]    = pa0.x;
            As[nxt][acol+1][arow]    = pa0.y;
            As[nxt][acol+2][arow]    = pa0.z;
            As[nxt][acol+3][arow]    = pa0.w;
            As[nxt][acol+0][arow+64] = pa1.x;
            As[nxt][acol+1][arow+64] = pa1.y;
            As[nxt][acol+2][arow+64] = pa1.z;
            As[nxt][acol+3][arow+64] = pa1.w;
            *(float4*)&Bs[nxt][brow][bcol]   = pb0;
            *(float4*)&Bs[nxt][brow+8][bcol] = pb1;
        }
        __syncthreads();
    }

    // epilogue: bias + optional relu, float4 stores
    float4 bv0 = *(const float4*)(bias + col0 + tx4);
    float4 bv1 = *(const float4*)(bias + col0 + tx4 + 64);
    #pragma unroll
    for (int ih = 0; ih < 2; ih++) {
        #pragma unroll
        for (int i = 0; i < 4; i++) {
            int r = row0 + ih*64 + ty4 + i;
            float* crow = C + (size_t)r * M + col0;
            #pragma unroll
            for (int jh = 0; jh < 2; jh++) {
                float4 bb = jh ? bv1 : bv0;
                float4 v;
                v.x = acc[ih*4+i][jh*4+0] + bb.x;
                v.y = acc[ih*4+i][jh*4+1] + bb.y;
                v.z = acc[ih*4+i][jh*4+2] + bb.z;
                v.w = acc[ih*4+i][jh*4+3] + bb.w;
                if (relu) {
                    v.x = fmaxf(v.x, 0.0f); v.y = fmaxf(v.y, 0.0f);
                    v.z = fmaxf(v.z, 0.0f); v.w = fmaxf(v.w, 0.0f);
                }
                *(float4*)(crow + jh*64 + tx4) = v;
            }
        }
    }
}

// ---------------- fused causal flash attention ----------------
// grid: (S/64, B*H); block 16x16. Each block: one (b,h), 64 queries.
__global__ void attn_kernel(const float* __restrict__ Q, const float* __restrict__ K,
                            const float* __restrict__ V, float* __restrict__ O) {
    __shared__ float Qs[64*64];   // [d][q] swizzled
    __shared__ float KP[64*64];   // K as [d][k] swizzled; reused as P [k][q] swizzled
    __shared__ float Vs[64*64];   // [k][d] natural

    int tx = threadIdx.x, ty = threadIdx.y;
    int tid = ty*16 + tx;
    int lr  = tid >> 4;
    int d4  = (tid & 15) * 4;

    int bh = blockIdx.y;
    int b  = bh >> 3;
    int hh = bh & 7;
    int qt = blockIdx.x;
    int q0 = qt * 64;
    size_t base = ((size_t)b * SS) * QKV + hh * HDIM;

    #pragma unroll
    for (int rep = 0; rep < 4; rep++) {
        int q = rep*16 + lr;
        float4 v4 = *(const float4*)(Q + base + (size_t)(q0 + q)*QKV + d4);
        Qs[SWZ(d4+0, q)] = v4.x;
        Qs[SWZ(d4+1, q)] = v4.y;
        Qs[SWZ(d4+2, q)] = v4.z;
        Qs[SWZ(d4+3, q)] = v4.w;
    }

    float m[4], l[4], o[4][4];
    #pragma unroll
    for (int i = 0; i < 4; i++) {
        m[i] = -1e30f; l[i] = 0.0f;
        #pragma unroll
        for (int j = 0; j < 4; j++) o[i][j] = 0.0f;
    }

    for (int kt = 0; kt <= qt; kt++) {
        __syncthreads();
        #pragma unroll
        for (int rep = 0; rep < 4; rep++) {
            int k = rep*16 + lr;
            size_t roff = base + (size_t)(kt*64 + k)*QKV + d4;
            float4 kv = *(const float4*)(K + roff);
            KP[SWZ(d4+0, k)] = kv.x;
            KP[SWZ(d4+1, k)] = kv.y;
            KP[SWZ(d4+2, k)] = kv.z;
            KP[SWZ(d4+3, k)] = kv.w;
            float4 vv = *(const float4*)(V + roff);
            *(float4*)&Vs[k*64 + d4] = vv;
        }
        __syncthreads();

        float s[4][4];
        #pragma unroll
        for (int i = 0; i < 4; i++)
            #pragma unroll
            for (int j = 0; j < 4; j++) s[i][j] = 0.0f;
        #pragma unroll 8
        for (int d = 0; d < 64; d++) {
            float a[4], bb[4];
            #pragma unroll
            for (int i = 0; i < 4; i++) a[i]  = Qs[SWZ(d, ty*4 + i)];
            #pragma unroll
            for (int j = 0; j < 4; j++) bb[j] = KP[SWZ(d, tx*4 + j)];
            #pragma unroll
            for (int i = 0; i < 4; i++)
                #pragma unroll
                for (int j = 0; j < 4; j++) s[i][j] = fmaf(a[i], bb[j], s[i][j]);
        }
        bool diag = (kt == qt);
        #pragma unroll
        for (int i = 0; i < 4; i++)
            #pragma unroll
            for (int j = 0; j < 4; j++) {
                float sv = s[i][j] * 0.125f;
                if (diag && (tx*4 + j) > (ty*4 + i)) sv = -1e30f;
                s[i][j] = sv;
            }

        float pr[4][4];
        #pragma unroll
        for (int i = 0; i < 4; i++) {
            float mx = s[i][0];
            #pragma unroll
            for (int j = 1; j < 4; j++) mx = fmaxf(mx, s[i][j]);
            #pragma unroll
            for (int off = 8; off >= 1; off >>= 1)
                mx = fmaxf(mx, __shfl_xor_sync(0xffffffffu, mx, off, 16));
            float mn = fmaxf(m[i], mx);
            float corr = __expf(m[i] - mn);
            l[i] *= corr;
            #pragma unroll
            for (int j = 0; j < 4; j++) o[i][j] *= corr;
            float rs = 0.0f;
            #pragma unroll
            for (int j = 0; j < 4; j++) { pr[i][j] = __expf(s[i][j] - mn); rs += pr[i][j]; }
            #pragma unroll
            for (int off = 8; off >= 1; off >>= 1)
                rs += __shfl_xor_sync(0xffffffffu, rs, off, 16);
            l[i] += rs;
            m[i] = mn;
        }

        __syncthreads();
        #pragma unroll
        for (int i = 0; i < 4; i++)
            #pragma unroll
            for (int j = 0; j < 4; j++)
                KP[SWZ(tx*4 + j, ty*4 + i)] = pr[i][j];
        __syncthreads();

        #pragma unroll 8
        for (int kk = 0; kk < 64; kk++) {
            float a[4], bb[4];
            #pragma unroll
            for (int i = 0; i < 4; i++) a[i]  = KP[SWZ(kk, ty*4 + i)];
            #pragma unroll
            for (int j = 0; j < 4; j++) bb[j] = Vs[kk*64 + tx*4 + j];
            #pragma unroll
            for (int i = 0; i < 4; i++)
                #pragma unroll
                for (int j = 0; j < 4; j++) o[i][j] = fmaf(a[i], bb[j], o[i][j]);
        }
    }

    #pragma unroll
    for (int i = 0; i < 4; i++) {
        float inv = 1.0f / l[i];
        int q = q0 + ty*4 + i;
        #pragma unroll
        for (int j = 0; j < 4; j++)
            O[base + (size_t)q*QKV + tx*4 + j] = o[i][j] * inv;
    }
}

// ---------------- fused residual add + LayerNorm (in place on h) ----------------
__global__ void add_ln_kernel(float* __restrict__ h, const float* __restrict__ r,
                              const float* __restrict__ s, const float* __restrict__ b) {
    __shared__ float red[12];
    int t = blockIdx.x;
    int d = threadIdx.x;
    int lane = d & 31, w = d >> 5;

    float v = h[(size_t)t*DM + d] + r[(size_t)t*DM + d];

    float sum = v;
    #pragma unroll
    for (int off = 16; off >= 1; off >>= 1) sum += __shfl_xor_sync(0xffffffffu, sum, off);
    if (lane == 0) red[w] = sum;
    __syncthreads();
    if (d == 0) { float tt = 0; for (int i = 0; i < 8; i++) tt += red[i]; red[8] = tt; }
    __syncthreads();
    float mean = red[8] * (1.0f/DM);

    float dv = v - mean;
    float sq = dv*dv;
    #pragma unroll
    for (int off = 16; off >= 1; off >>= 1) sq += __shfl_xor_sync(0xffffffffu, sq, off);
    if (lane == 0) red[w] = sq;
    __syncthreads();
    if (d == 0) { float tt = 0; for (int i = 0; i < 8; i++) tt += red[i]; red[9] = tt; }
    __syncthreads();
    float var = red[9] * (1.0f/DM);

    h[(size_t)t*DM + d] = dv * rsqrtf(var + 1e-5f) * s[d] + b[d];
}

// ---------------- launch ----------------
extern "C" void kernel_launch(void* const* d_in, const int* in_sizes, int n_in,
                              void* d_out, int out_size) {
    (void)in_sizes; (void)n_in; (void)out_size;
    const int*   x    = (const int*)  d_in[0];
    const float* emb  = (const float*)d_in[1];
    const float* wq   = (const float*)d_in[2];
    const float* bq   = (const float*)d_in[3];
    const float* wk   = (const float*)d_in[4];
    const float* bk   = (const float*)d_in[5];
    const float* wv   = (const float*)d_in[6];
    const float* bv   = (const float*)d_in[7];
    const float* wo   = (const float*)d_in[8];
    const float* bo   = (const float*)d_in[9];
    const float* ln1s = (const float*)d_in[10];
    const float* ln1b = (const float*)d_in[11];
    const float* w1   = (const float*)d_in[12];
    const float* b1   = (const float*)d_in[13];
    const float* w2   = (const float*)d_in[14];
    const float* b2   = (const float*)d_in[15];
    const float* ln2s = (const float*)d_in[16];
    const float* ln2b = (const float*)d_in[17];
    const float* ow   = (const float*)d_in[18];
    const float* ob   = (const float*)d_in[19];
    float* out = (float*)d_out;

    float *h, *q, *k, *v, *o, *ff, *p, *pe;
    cudaGetSymbolAddress((void**)&h,  g_h);
    cudaGetSymbolAddress((void**)&q,  g_q);
    cudaGetSymbolAddress((void**)&k,  g_k);
    cudaGetSymbolAddress((void**)&v,  g_v);
    cudaGetSymbolAddress((void**)&o,  g_o);
    cudaGetSymbolAddress((void**)&ff, g_ff);
    cudaGetSymbolAddress((void**)&p,  g_p);
    cudaGetSymbolAddress((void**)&pe, g_pe);

    dim3 blk(16, 16);

    pe_kernel   <<<SS, DM>>>(pe);
    embed_kernel<<<NT, DM>>>(x, emb, pe, h);

    for (int i = 0; i < NLAYER; i++) {
        gemm_bias<<<dim3(QKV/BN, NT/BM), 256>>>(h, wq + (size_t)i*DM*QKV, bq + i*QKV, q, QKV, DM, 0);
        gemm_bias<<<dim3(QKV/BN, NT/BM), 256>>>(h, wk + (size_t)i*DM*QKV, bk + i*QKV, k, QKV, DM, 0);
        gemm_bias<<<dim3(QKV/BN, NT/BM), 256>>>(h, wv + (size_t)i*DM*QKV, bv + i*QKV, v, QKV, DM, 0);
        attn_kernel<<<dim3(SS/64, NB*NH), blk>>>(q, k, v, o);
        gemm_bias<<<dim3(DM/BN, NT/BM), 256>>>(o, wo + (size_t)i*QKV*DM, bo + i*DM, p, DM, QKV, 0);
        add_ln_kernel<<<NT, DM>>>(h, p, ln1s + i*DM, ln1b + i*DM);
        gemm_bias<<<dim3(FFD/BN, NT/BM), 256>>>(h, w1 + (size_t)i*DM*FFD, b1 + i*FFD, ff, FFD, DM, 1);
        gemm_bias<<<dim3(DM/BN, NT/BM), 256>>>(ff, w2 + (size_t)i*FFD*DM, b2 + i*DM, p, DM, FFD, 0);
        add_ln_kernel<<<NT, DM>>>(h, p, ln2s + i*DM, ln2b + i*DM);
    }

    gemm_bias<<<dim3(OUTD/BN, NT/BM), 256>>>(h, ow, ob, out, OUTD, DM, 0);
}

// round 6
// speedup vs baseline: 1.8417x; 1.3728x over previous
#include <cuda_runtime.h>
#include <cuda_bf16.h>
#include <math.h>
#include <stdint.h>

#define NB 32
#define SS 512
#define DM 256
#define NH 8
#define HDIM 64
#define NLAYER 5
#define FFD 1024
#define OUTD 4096
#define NT (NB*SS)     /* 16384 tokens */
#define QKV 512        /* H*HD */

// ---------------- scratch (no allocations allowed) ----------------
__device__ float g_h [NT*DM];
__device__ float g_q [NT*QKV];
__device__ float g_k [NT*QKV];
__device__ float g_v [NT*QKV];
__device__ float g_p [NT*DM];
__device__ float g_pe[SS*DM];
__device__ __nv_bfloat16 g_hh [NT*DM];
__device__ __nv_bfloat16 g_hl [NT*DM];
__device__ __nv_bfloat16 g_ohi[NT*QKV];
__device__ __nv_bfloat16 g_olo[NT*QKV];
__device__ __nv_bfloat16 g_ffh[NT*FFD];
__device__ __nv_bfloat16 g_ffl[NT*FFD];
#define WT_TOTAL 6291456
__device__ __nv_bfloat16 g_wth[WT_TOTAL];
__device__ __nv_bfloat16 g_wtl[WT_TOTAL];

// weight-transpose offsets (elements)
#define WQT(i) ((size_t)(i)*1048576)
#define WKT(i) (WQT(i)+131072)
#define WVT(i) (WQT(i)+262144)
#define WOT(i) (WQT(i)+393216)
#define W1T(i) (WQT(i)+524288)
#define W2T(i) (WQT(i)+786432)
#define OWT    ((size_t)5242880)

// ---------------- helpers ----------------
__device__ __forceinline__ uint32_t smem_u32(const void* p) {
    uint32_t a;
    asm("{ .reg .u64 t; cvta.to.shared.u64 t, %1; cvt.u32.u64 %0, t; }" : "=r"(a) : "l"(p));
    return a;
}
__device__ __forceinline__ void split_bf16(float v, __nv_bfloat16& hi, __nv_bfloat16& lo) {
    hi = __float2bfloat16(v);
    lo = __float2bfloat16(v - __bfloat162float(hi));
}
__device__ __forceinline__ void cp16(uint32_t dst, const void* src) {
    asm volatile("cp.async.cg.shared.global [%0], [%1], 16;" :: "r"(dst), "l"(src));
}
__device__ __forceinline__ void ldmx4(uint32_t* r, uint32_t addr) {
    asm volatile("ldmatrix.sync.aligned.m8n8.x4.shared.b16 {%0,%1,%2,%3}, [%4];"
        : "=r"(r[0]), "=r"(r[1]), "=r"(r[2]), "=r"(r[3]) : "r"(addr));
}
__device__ __forceinline__ void mma16816(float* d, const uint32_t* a, const uint32_t* b) {
    asm volatile("mma.sync.aligned.m16n8k16.row.col.f32.bf16.bf16.f32 "
        "{%0,%1,%2,%3}, {%4,%5,%6,%7}, {%8,%9}, {%0,%1,%2,%3};"
        : "+f"(d[0]), "+f"(d[1]), "+f"(d[2]), "+f"(d[3])
        : "r"(a[0]), "r"(a[1]), "r"(a[2]), "r"(a[3]), "r"(b[0]), "r"(b[1]));
}

// ---------------- positional encoding ----------------
__global__ void pe_kernel(float* __restrict__ pe) {
    int s = blockIdx.x, d = threadIdx.x;
    int i = d >> 1;
    float div = powf(10000.0f, (float)(2*i) / (float)DM);
    float ang = (float)s / div;
    pe[s*DM + d] = (d & 1) ? cosf(ang) : sinf(ang);
}

// ---------------- embedding + PE (+ bf16 split) ----------------
__global__ void embed_kernel(const int* __restrict__ x, const float* __restrict__ emb,
                             const float* __restrict__ pe, float* __restrict__ h,
                             __nv_bfloat16* __restrict__ hh, __nv_bfloat16* __restrict__ hl) {
    int t = blockIdx.x, d = threadIdx.x;
    int tok = x[t];
    int s = t & (SS-1);
    float v = emb[tok*DM + d] + pe[s*DM + d];
    h[(size_t)t*DM + d] = v;
    __nv_bfloat16 hi, lo; split_bf16(v, hi, lo);
    hh[(size_t)t*DM + d] = hi;
    hl[(size_t)t*DM + d] = lo;
}

// ---------------- weight transpose + split: W[K,N] -> T[N,K] bf16 hi/lo ----------------
__global__ void wsplit(const float* __restrict__ W, __nv_bfloat16* __restrict__ Thi,
                       __nv_bfloat16* __restrict__ Tlo, int K, int N) {
    __shared__ float t[32][33];
    int k0 = blockIdx.x*32, n0 = blockIdx.y*32;
    int tx = threadIdx.x, ty = threadIdx.y;  // 32 x 8
    #pragma unroll
    for (int i = 0; i < 32; i += 8)
        t[ty+i][tx] = W[(size_t)(k0+ty+i)*N + n0+tx];
    __syncthreads();
    #pragma unroll
    for (int i = 0; i < 32; i += 8) {
        float v = t[tx][ty+i];
        __nv_bfloat16 hi, lo; split_bf16(v, hi, lo);
        Thi[(size_t)(n0+ty+i)*K + k0+tx] = hi;
        Tlo[(size_t)(n0+ty+i)*K + k0+tx] = lo;
    }
}

// ---------------- HMMA bf16x3 GEMM (mma.sync path, works at compute_103) ----------------
// C[R, Ncols] = A[R, K] @ B^T (B transposed: [Ncols, K]), bf16 hi/lo split.
// CTA 128x128, BK=32, 256 threads, warp tile 64x32 (warp grid 2m x 4n).
#define GBM 128
#define GBN 128
#define GBK 32
#define ROWB 80                    /* 64B data + 16B pad: ldmatrix conflict-free */
#define TILEB (128*ROWB)           /* 10240 bytes */
#define OFF_AHI 0
#define OFF_ALO TILEB
#define OFF_BHI (2*TILEB)
#define OFF_BLO (3*TILEB)
#define STAGEB (4*TILEB)           /* 40960 */
#define GSMEM (2*STAGEB)           /* 81920 */

__global__ void __launch_bounds__(256, 1)
gemm_mma(const __nv_bfloat16* __restrict__ Ahi, const __nv_bfloat16* __restrict__ Alo,
         const __nv_bfloat16* __restrict__ Bhi, const __nv_bfloat16* __restrict__ Blo,
         const float* __restrict__ bias,
         float* __restrict__ Cf, __nv_bfloat16* __restrict__ Chi, __nv_bfloat16* __restrict__ Clo,
         int Ncols, int K, int mode, int relu) {
    extern __shared__ char smem[];
    uint32_t sb = smem_u32(smem);
    int tid = threadIdx.x;
    int lane = tid & 31;
    int wid = tid >> 5;
    int warp_m = wid & 1;          // 0..1 -> 64-row half
    int warp_n = wid >> 1;         // 0..3 -> 32-col quarter
    int row0 = blockIdx.y * GBM;
    int col0 = blockIdx.x * GBN;

    // cp.async loader mapping: unit u: row = u>>2, 16B-chunk = u&3 (row has 64B)
    int lr  = tid >> 2;            // 0..63
    int lc  = tid & 3;             // 0..3
    uint32_t sm_off0 = (uint32_t)(lr * ROWB + lc * 16);
    uint32_t sm_off1 = (uint32_t)((lr + 64) * ROWB + lc * 16);

#define LOAD_STAGE(bufidx, chunk) do { \
    uint32_t so = sb + (uint32_t)(bufidx)*STAGEB; \
    int kc = (chunk)*GBK + lc*8; \
    size_t ga0 = (size_t)(row0 + lr)      * K + kc; \
    size_t ga1 = (size_t)(row0 + lr + 64) * K + kc; \
    size_t gb0 = (size_t)(col0 + lr)      * K + kc; \
    size_t gb1 = (size_t)(col0 + lr + 64) * K + kc; \
    cp16(so + OFF_AHI + sm_off0, Ahi + ga0); \
    cp16(so + OFF_AHI + sm_off1, Ahi + ga1); \
    cp16(so + OFF_ALO + sm_off0, Alo + ga0); \
    cp16(so + OFF_ALO + sm_off1, Alo + ga1); \
    cp16(so + OFF_BHI + sm_off0, Bhi + gb0); \
    cp16(so + OFF_BHI + sm_off1, Bhi + gb1); \
    cp16(so + OFF_BLO + sm_off0, Blo + gb0); \
    cp16(so + OFF_BLO + sm_off1, Blo + gb1); \
} while(0)

    // ldmatrix per-lane base offsets
    // A (m16k16 tile): lanes 0-7 m0-7/klo, 8-15 m8-15/klo, 16-23 m0-7/khi, 24-31 m8-15/khi
    uint32_t a_row = (uint32_t)(warp_m*64 + (lane & 15));
    uint32_t a_off = a_row * ROWB + ((uint32_t)(lane >> 4)) * 16;
    // B (n16k16 two-frag tile): lanes 0-7 n0-7/klo, 8-15 n0-7/khi, 16-23 n8-15/klo, 24-31 n8-15/khi
    uint32_t b_row = (uint32_t)(warp_n*32 + (lane & 7) + ((lane >> 4) << 3));
    uint32_t b_off = b_row * ROWB + ((uint32_t)((lane >> 3) & 1)) * 16;

    float acc[4][4][4];
    #pragma unroll
    for (int i = 0; i < 4; i++)
        #pragma unroll
        for (int j = 0; j < 4; j++)
            #pragma unroll
            for (int e = 0; e < 4; e++) acc[i][j][e] = 0.0f;

    int nch = K / GBK;
    LOAD_STAGE(0, 0);
    asm volatile("cp.async.commit_group;" ::: "memory");

    for (int c = 0; c < nch; c++) {
        int buf = c & 1;
        asm volatile("cp.async.wait_group 0;" ::: "memory");
        __syncthreads();
        if (c + 1 < nch) {
            LOAD_STAGE((c + 1) & 1, c + 1);
            asm volatile("cp.async.commit_group;" ::: "memory");
        }

        uint32_t so = sb + (uint32_t)buf * STAGEB;
        #pragma unroll
        for (int s = 0; s < 2; s++) {
            uint32_t ks = (uint32_t)(s * 32);
            uint32_t ah[4][4], al[4][4];
            #pragma unroll
            for (int mi = 0; mi < 4; mi++) {
                uint32_t ao = a_off + (uint32_t)(mi*16) * ROWB + ks;
                ldmx4(ah[mi], so + OFF_AHI + ao);
                ldmx4(al[mi], so + OFF_ALO + ao);
            }
            uint32_t bh[2][4], bl[2][4];
            #pragma unroll
            for (int nt = 0; nt < 2; nt++) {
                uint32_t bo = b_off + (uint32_t)(nt*16) * ROWB + ks;
                ldmx4(bh[nt], so + OFF_BHI + bo);
                ldmx4(bl[nt], so + OFF_BLO + bo);
            }
            #pragma unroll
            for (int mi = 0; mi < 4; mi++)
                #pragma unroll
                for (int nj = 0; nj < 4; nj++) {
                    const uint32_t* ph = &bh[nj >> 1][(nj & 1) * 2];
                    const uint32_t* pl = &bl[nj >> 1][(nj & 1) * 2];
                    mma16816(acc[mi][nj], ah[mi], ph);
                    mma16816(acc[mi][nj], ah[mi], pl);
                    mma16816(acc[mi][nj], al[mi], ph);
                }
        }
        __syncthreads();
    }

    // epilogue: c-frag lane l: {c0,c1}: m=l>>2, n=2(l&3)+{0,1}; {c2,c3}: m+8
    int em = row0 + warp_m*64 + (lane >> 2);
    int en = col0 + warp_n*32 + (lane & 3) * 2;
    #pragma unroll
    for (int mi = 0; mi < 4; mi++) {
        #pragma unroll
        for (int nj = 0; nj < 4; nj++) {
            int cc = en + nj*8;
            float b0 = bias[cc], b1 = bias[cc + 1];
            #pragma unroll
            for (int half = 0; half < 2; half++) {
                int rr = em + mi*16 + half*8;
                float v0 = acc[mi][nj][half*2 + 0] + b0;
                float v1 = acc[mi][nj][half*2 + 1] + b1;
                if (relu) { v0 = fmaxf(v0, 0.0f); v1 = fmaxf(v1, 0.0f); }
                size_t idx = (size_t)rr * Ncols + cc;
                if (mode == 0) {
                    *(float2*)(Cf + idx) = make_float2(v0, v1);
                } else {
                    __nv_bfloat16 h0, l0, h1, l1;
                    split_bf16(v0, h0, l0); split_bf16(v1, h1, l1);
                    __nv_bfloat162 ph; ph.x = h0; ph.y = h1;
                    __nv_bfloat162 pl; pl.x = l0; pl.y = l1;
                    *(__nv_bfloat162*)(Chi + idx) = ph;
                    *(__nv_bfloat162*)(Clo + idx) = pl;
                }
            }
        }
    }
#undef LOAD_STAGE
}

// ---------------- fused causal flash attention (fp32 SIMT), writes split-bf16 O ----------------
__device__ __forceinline__ int SWZ(int row, int col) { return row*64 + ((col + row) & 63); }

__global__ void attn_kernel(const float* __restrict__ Q, const float* __restrict__ K,
                            const float* __restrict__ V,
                            __nv_bfloat16* __restrict__ Ohi, __nv_bfloat16* __restrict__ Olo) {
    __shared__ float Qs[64*64];
    __shared__ float KP[64*64];
    __shared__ float Vs[64*64];

    int tx = threadIdx.x, ty = threadIdx.y;
    int tid = ty*16 + tx;
    int lr  = tid >> 4;
    int d4  = (tid & 15) * 4;

    int bh = blockIdx.y;
    int b  = bh >> 3;
    int hh = bh & 7;
    int qt = blockIdx.x;
    int q0 = qt * 64;
    size_t base = ((size_t)b * SS) * QKV + hh * HDIM;

    #pragma unroll
    for (int rep = 0; rep < 4; rep++) {
        int q = rep*16 + lr;
        float4 v4 = *(const float4*)(Q + base + (size_t)(q0 + q)*QKV + d4);
        Qs[SWZ(d4+0, q)] = v4.x; Qs[SWZ(d4+1, q)] = v4.y;
        Qs[SWZ(d4+2, q)] = v4.z; Qs[SWZ(d4+3, q)] = v4.w;
    }

    float m[4], l[4], o[4][4];
    #pragma unroll
    for (int i = 0; i < 4; i++) {
        m[i] = -1e30f; l[i] = 0.0f;
        #pragma unroll
        for (int j = 0; j < 4; j++) o[i][j] = 0.0f;
    }

    for (int kt = 0; kt <= qt; kt++) {
        __syncthreads();
        #pragma unroll
        for (int rep = 0; rep < 4; rep++) {
            int k = rep*16 + lr;
            size_t roff = base + (size_t)(kt*64 + k)*QKV + d4;
            float4 kv = *(const float4*)(K + roff);
            KP[SWZ(d4+0, k)] = kv.x; KP[SWZ(d4+1, k)] = kv.y;
            KP[SWZ(d4+2, k)] = kv.z; KP[SWZ(d4+3, k)] = kv.w;
            float4 vv = *(const float4*)(V + roff);
            *(float4*)&Vs[k*64 + d4] = vv;
        }
        __syncthreads();

        float s[4][4];
        #pragma unroll
        for (int i = 0; i < 4; i++)
            #pragma unroll
            for (int j = 0; j < 4; j++) s[i][j] = 0.0f;
        #pragma unroll 8
        for (int d = 0; d < 64; d++) {
            float a[4], bb[4];
            #pragma unroll
            for (int i = 0; i < 4; i++) a[i]  = Qs[SWZ(d, ty*4 + i)];
            #pragma unroll
            for (int j = 0; j < 4; j++) bb[j] = KP[SWZ(d, tx*4 + j)];
            #pragma unroll
            for (int i = 0; i < 4; i++)
                #pragma unroll
                for (int j = 0; j < 4; j++) s[i][j] = fmaf(a[i], bb[j], s[i][j]);
        }
        bool diag = (kt == qt);
        #pragma unroll
        for (int i = 0; i < 4; i++)
            #pragma unroll
            for (int j = 0; j < 4; j++) {
                float sv = s[i][j] * 0.125f;
                if (diag && (tx*4 + j) > (ty*4 + i)) sv = -1e30f;
                s[i][j] = sv;
            }

        float pr[4][4];
        #pragma unroll
        for (int i = 0; i < 4; i++) {
            float mx = s[i][0];
            #pragma unroll
            for (int j = 1; j < 4; j++) mx = fmaxf(mx, s[i][j]);
            #pragma unroll
            for (int off = 8; off >= 1; off >>= 1)
                mx = fmaxf(mx, __shfl_xor_sync(0xffffffffu, mx, off, 16));
            float mn = fmaxf(m[i], mx);
            float corr = __expf(m[i] - mn);
            l[i] *= corr;
            #pragma unroll
            for (int j = 0; j < 4; j++) o[i][j] *= corr;
            float rs = 0.0f;
            #pragma unroll
            for (int j = 0; j < 4; j++) { pr[i][j] = __expf(s[i][j] - mn); rs += pr[i][j]; }
            #pragma unroll
            for (int off = 8; off >= 1; off >>= 1)
                rs += __shfl_xor_sync(0xffffffffu, rs, off, 16);
            l[i] += rs;
            m[i] = mn;
        }

        __syncthreads();
        #pragma unroll
        for (int i = 0; i < 4; i++)
            #pragma unroll
            for (int j = 0; j < 4; j++)
                KP[SWZ(tx*4 + j, ty*4 + i)] = pr[i][j];
        __syncthreads();

        #pragma unroll 8
        for (int kk = 0; kk < 64; kk++) {
            float a[4], bb[4];
            #pragma unroll
            for (int i = 0; i < 4; i++) a[i]  = KP[SWZ(kk, ty*4 + i)];
            #pragma unroll
            for (int j = 0; j < 4; j++) bb[j] = Vs[kk*64 + tx*4 + j];
            #pragma unroll
            for (int i = 0; i < 4; i++)
                #pragma unroll
                for (int j = 0; j < 4; j++) o[i][j] = fmaf(a[i], bb[j], o[i][j]);
        }
    }

    #pragma unroll
    for (int i = 0; i < 4; i++) {
        float inv = 1.0f / l[i];
        int q = q0 + ty*4 + i;
        #pragma unroll
        for (int j = 0; j < 4; j++) {
            float v = o[i][j] * inv;
            __nv_bfloat16 hi, lo; split_bf16(v, hi, lo);
            size_t idx = base + (size_t)q*QKV + tx*4 + j;
            Ohi[idx] = hi;
            Olo[idx] = lo;
        }
    }
}

// ---------------- fused residual add + LayerNorm (+ bf16 split) ----------------
__global__ void add_ln_kernel(float* __restrict__ h, const float* __restrict__ r,
                              const float* __restrict__ s, const float* __restrict__ b,
                              __nv_bfloat16* __restrict__ hh, __nv_bfloat16* __restrict__ hl) {
    __shared__ float red[12];
    int t = blockIdx.x;
    int d = threadIdx.x;
    int lane = d & 31, w = d >> 5;

    float v = h[(size_t)t*DM + d] + r[(size_t)t*DM + d];

    float sum = v;
    #pragma unroll
    for (int off = 16; off >= 1; off >>= 1) sum += __shfl_xor_sync(0xffffffffu, sum, off);
    if (lane == 0) red[w] = sum;
    __syncthreads();
    if (d == 0) { float tt = 0; for (int i = 0; i < 8; i++) tt += red[i]; red[8] = tt; }
    __syncthreads();
    float mean = red[8] * (1.0f/DM);

    float dv = v - mean;
    float sq = dv*dv;
    #pragma unroll
    for (int off = 16; off >= 1; off >>= 1) sq += __shfl_xor_sync(0xffffffffu, sq, off);
    if (lane == 0) red[w] = sq;
    __syncthreads();
    if (d == 0) { float tt = 0; for (int i = 0; i < 8; i++) tt += red[i]; red[9] = tt; }
    __syncthreads();
    float var = red[9] * (1.0f/DM);

    float out = dv * rsqrtf(var + 1e-5f) * s[d] + b[d];
    h[(size_t)t*DM + d] = out;
    __nv_bfloat16 hi, lo; split_bf16(out, hi, lo);
    hh[(size_t)t*DM + d] = hi;
    hl[(size_t)t*DM + d] = lo;
}

// ---------------- launch ----------------
extern "C" void kernel_launch(void* const* d_in, const int* in_sizes, int n_in,
                              void* d_out, int out_size) {
    (void)in_sizes; (void)n_in; (void)out_size;
    const int*   x    = (const int*)  d_in[0];
    const float* emb  = (const float*)d_in[1];
    const float* wq   = (const float*)d_in[2];
    const float* bq   = (const float*)d_in[3];
    const float* wk   = (const float*)d_in[4];
    const float* bk   = (const float*)d_in[5];
    const float* wv   = (const float*)d_in[6];
    const float* bv   = (const float*)d_in[7];
    const float* wo   = (const float*)d_in[8];
    const float* bo   = (const float*)d_in[9];
    const float* ln1s = (const float*)d_in[10];
    const float* ln1b = (const float*)d_in[11];
    const float* w1   = (const float*)d_in[12];
    const float* b1   = (const float*)d_in[13];
    const float* w2   = (const float*)d_in[14];
    const float* b2   = (const float*)d_in[15];
    const float* ln2s = (const float*)d_in[16];
    const float* ln2b = (const float*)d_in[17];
    const float* ow   = (const float*)d_in[18];
    const float* ob   = (const float*)d_in[19];
    float* out = (float*)d_out;

    float *h, *q, *k, *v, *p, *pe;
    __nv_bfloat16 *hh, *hl, *ohi, *olo, *ffh, *ffl, *wth, *wtl;
    cudaGetSymbolAddress((void**)&h,  g_h);
    cudaGetSymbolAddress((void**)&q,  g_q);
    cudaGetSymbolAddress((void**)&k,  g_k);
    cudaGetSymbolAddress((void**)&v,  g_v);
    cudaGetSymbolAddress((void**)&p,  g_p);
    cudaGetSymbolAddress((void**)&pe, g_pe);
    cudaGetSymbolAddress((void**)&hh,  g_hh);
    cudaGetSymbolAddress((void**)&hl,  g_hl);
    cudaGetSymbolAddress((void**)&ohi, g_ohi);
    cudaGetSymbolAddress((void**)&olo, g_olo);
    cudaGetSymbolAddress((void**)&ffh, g_ffh);
    cudaGetSymbolAddress((void**)&ffl, g_ffl);
    cudaGetSymbolAddress((void**)&wth, g_wth);
    cudaGetSymbolAddress((void**)&wtl, g_wtl);

    static int smem_set = 0;
    if (!smem_set) {
        cudaFuncSetAttribute(gemm_mma, cudaFuncAttributeMaxDynamicSharedMemorySize, GSMEM);
        smem_set = 1;
    }

    dim3 wblk(32, 8);
    for (int i = 0; i < NLAYER; i++) {
        wsplit<<<dim3(DM/32,  QKV/32), wblk>>>(wq + (size_t)i*DM*QKV,  wth + WQT(i), wtl + WQT(i), DM,  QKV);
        wsplit<<<dim3(DM/32,  QKV/32), wblk>>>(wk + (size_t)i*DM*QKV,  wth + WKT(i), wtl + WKT(i), DM,  QKV);
        wsplit<<<dim3(DM/32,  QKV/32), wblk>>>(wv + (size_t)i*DM*QKV,  wth + WVT(i), wtl + WVT(i), DM,  QKV);
        wsplit<<<dim3(QKV/32, DM/32),  wblk>>>(wo + (size_t)i*QKV*DM,  wth + WOT(i), wtl + WOT(i), QKV, DM);
        wsplit<<<dim3(DM/32,  FFD/32), wblk>>>(w1 + (size_t)i*DM*FFD,  wth + W1T(i), wtl + W1T(i), DM,  FFD);
        wsplit<<<dim3(FFD/32, DM/32),  wblk>>>(w2 + (size_t)i*FFD*DM,  wth + W2T(i), wtl + W2T(i), FFD, DM);
    }
    wsplit<<<dim3(DM/32, OUTD/32), wblk>>>(ow, wth + OWT, wtl + OWT, DM, OUTD);

    pe_kernel   <<<SS, DM>>>(pe);
    embed_kernel<<<NT, DM>>>(x, emb, pe, h, hh, hl);

    dim3 ablk(16, 16);
    for (int i = 0; i < NLAYER; i++) {
        gemm_mma<<<dim3(QKV/GBN, NT/GBM), 256, GSMEM>>>(hh, hl, wth + WQT(i), wtl + WQT(i), bq + i*QKV, q, 0, 0, QKV, DM, 0, 0);
        gemm_mma<<<dim3(QKV/GBN, NT/GBM), 256, GSMEM>>>(hh, hl, wth + WKT(i), wtl + WKT(i), bk + i*QKV, k, 0, 0, QKV, DM, 0, 0);
        gemm_mma<<<dim3(QKV/GBN, NT/GBM), 256, GSMEM>>>(hh, hl, wth + WVT(i), wtl + WVT(i), bv + i*QKV, v, 0, 0, QKV, DM, 0, 0);
        attn_kernel<<<dim3(SS/64, NB*NH), ablk>>>(q, k, v, ohi, olo);
        gemm_mma<<<dim3(DM/GBN, NT/GBM), 256, GSMEM>>>(ohi, olo, wth + WOT(i), wtl + WOT(i), bo + i*DM, p, 0, 0, DM, QKV, 0, 0);
        add_ln_kernel<<<NT, DM>>>(h, p, ln1s + i*DM, ln1b + i*DM, hh, hl);
        gemm_mma<<<dim3(FFD/GBN, NT/GBM), 256, GSMEM>>>(hh, hl, wth + W1T(i), wtl + W1T(i), b1 + i*FFD, 0, ffh, ffl, FFD, DM, 1, 1);
        gemm_mma<<<dim3(DM/GBN, NT/GBM), 256, GSMEM>>>(ffh, ffl, wth + W2T(i), wtl + W2T(i), b2 + i*DM, p, 0, 0, DM, FFD, 0, 0);
        add_ln_kernel<<<NT, DM>>>(h, p, ln2s + i*DM, ln2b + i*DM, hh, hl);
    }

    gemm_mma<<<dim3(OUTD/GBN, NT/GBM), 256, GSMEM>>>(hh, hl, wth + OWT, wtl + OWT, ob, out, 0, 0, OUTD, DM, 0, 0);
}